// round 14
// baseline (speedup 1.0000x reference)
#include <cuda_runtime.h>
#include <cuda_bf16.h>
#include <math.h>

#define Nn   50000
#define Ee   500000
#define FIN  64
#define EIN  16
#define Hh   100
#define LL   2
#define BN_EPS 1e-5f

// ---------------- scratch (static device globals; no allocation) -------------
__device__ float g_h   [Nn * Hh];
__device__ float g_e   [(size_t)Ee * Hh];
__device__ float g_agg [Nn * Hh];
__device__ float g_zin [Nn * Hh];
__device__ float g_z   [Nn * Hh];
__device__ float g_Hab [Nn * 200];     // merged Ha|Hb; reused as HR (Nn*100) at readout
__device__ float g_stats[2 * Hh];

// ---------------- small kernels ----------------------------------------------
__global__ void zero2_k(float* __restrict__ agg, float* __restrict__ st) {
    int i = blockIdx.x * blockDim.x + threadIdx.x;
    if (i < Nn * Hh) agg[i] = 0.f;
    if (i < 2 * Hh) st[i] = 0.f;
}

// zin = h + agg; also zero stats for this layer's gine epilogue
__global__ void add_st_k(const float* __restrict__ h, const float* __restrict__ agg,
                         float* __restrict__ zin, float* __restrict__ st) {
    int i = blockIdx.x * blockDim.x + threadIdx.x;
    if (i < Nn * Hh) zin[i] = h[i] + agg[i];
    if (i < 2 * Hh) st[i] = 0.f;
}

// h = (h + relu(batchnorm(z))) * 0.5 ; also zero agg for next layer's scatter
__global__ void hupd_k(float* __restrict__ h, const float* __restrict__ z,
                       const float* __restrict__ stats, float* __restrict__ agg,
                       const float* __restrict__ gamma, const float* __restrict__ beta) {
    int idx = blockIdx.x * blockDim.x + threadIdx.x;
    if (idx >= Nn * Hh) return;
    int j = idx % Hh;
    float mu  = stats[j] * (1.0f / Nn);
    float var = fmaf(-mu, mu, stats[Hh + j] * (1.0f / Nn));
    float zn  = (z[idx] - mu) * rsqrtf(var + BN_EPS) * gamma[j] + beta[j];
    h[idx] = (h[idx] + fmaxf(zn, 0.f)) * 0.5f;
    agg[idx] = 0.f;
}

// ---------------- bf16x2 split machinery --------------------------------------
__device__ __forceinline__ void mma16b(float* c, unsigned a0, unsigned a1,
                                       unsigned a2, unsigned a3,
                                       unsigned b0, unsigned b1) {
    asm volatile(
        "mma.sync.aligned.m16n8k16.row.col.f32.bf16.bf16.f32 "
        "{%0,%1,%2,%3}, {%4,%5,%6,%7}, {%8,%9}, {%0,%1,%2,%3};"
        : "+f"(c[0]), "+f"(c[1]), "+f"(c[2]), "+f"(c[3])
        : "r"(a0), "r"(a1), "r"(a2), "r"(a3), "r"(b0), "r"(b1));
}

// split a float2 (k-even, k-odd) into packed bf16x2 hi (truncation) + lo (RN)
template<bool RELU>
__device__ __forceinline__ void split2(float2 p, unsigned& hi, unsigned& lo) {
    if (RELU) { p.x = fmaxf(p.x, 0.f); p.y = fmaxf(p.y, 0.f); }
    unsigned bx = __float_as_uint(p.x), by = __float_as_uint(p.y);
    unsigned h;
    asm("prmt.b32 %0, %1, %2, 0x7632;" : "=r"(h) : "r"(bx), "r"(by));
    float hx = __uint_as_float(bx & 0xFFFF0000u);
    float hy = __uint_as_float(by & 0xFFFF0000u);
    float lx = p.x - hx, ly = p.y - hy;
    unsigned l;
    asm("cvt.rn.bf16x2.f32 %0, %1, %2;" : "=r"(l) : "f"(ly), "f"(lx));
    hi = h; lo = l;
}

// fragment pack core: given 4 weight values -> uint4 {b0hi,b1hi,b0lo,b1lo}
__device__ __forceinline__ uint4 pack4(const float w[4]) {
    float lo[4];
    #pragma unroll
    for (int q = 0; q < 4; q++) {
        __nv_bfloat16 hq = __float2bfloat16(w[q]);
        lo[q] = w[q] - __bfloat162float(hq);
    }
    unsigned hb[2], lb[2];
    #pragma unroll
    for (int pi = 0; pi < 2; pi++) {
        __nv_bfloat162 hh = {__float2bfloat16(w[pi * 2]), __float2bfloat16(w[pi * 2 + 1])};
        __nv_bfloat162 ll = {__float2bfloat16(lo[pi * 2]), __float2bfloat16(lo[pi * 2 + 1])};
        hb[pi] = *(unsigned*)&hh;
        lb[pi] = *(unsigned*)&ll;
    }
    return make_uint4(hb[0], hb[1], lb[0], lb[1]);
}

// pack one W [KIN x NV] (row stride NV)
template<int KIN, int KST, int NT, int NV, int NTHR>
__device__ __forceinline__ void pack_w(const float* __restrict__ W, float* Wp, int tid) {
    for (int idx = tid; idx < KST * NT * 32; idx += NTHR) {
        int ks  = idx / (NT * 32);
        int rem = idx - ks * NT * 32;
        int nt = rem >> 5, l = rem & 31;
        int tg = l & 3, g = l >> 2;
        int n = nt * 8 + g;
        int k0 = ks * 16 + 2 * tg;
        float w[4];
        #pragma unroll
        for (int q = 0; q < 4; q++) {
            int k = k0 + (q >> 1) * 8 + (q & 1);
            w[q] = (k < KIN && n < NV) ? W[k * NV + n] : 0.f;
        }
        ((uint4*)Wp)[idx] = pack4(w);
    }
}

// pack two W halves side by side: n<NVH from W1[k*NVH+n], NVH<=n<2NVH from W2[k*NVH+n-NVH]
template<int KIN, int KST, int NT, int NVH, int NTHR>
__device__ __forceinline__ void pack_w2(const float* __restrict__ W1,
                                        const float* __restrict__ W2,
                                        float* Wp, int tid) {
    for (int idx = tid; idx < KST * NT * 32; idx += NTHR) {
        int ks  = idx / (NT * 32);
        int rem = idx - ks * NT * 32;
        int nt = rem >> 5, l = rem & 31;
        int tg = l & 3, g = l >> 2;
        int n = nt * 8 + g;
        int k0 = ks * 16 + 2 * tg;
        const float* Ws = (n < NVH) ? W1 : W2;
        int nn = (n < NVH) ? n : n - NVH;
        float w[4];
        #pragma unroll
        for (int q = 0; q < 4; q++) {
            int k = k0 + (q >> 1) * 8 + (q & 1);
            w[q] = (k < KIN && n < 2 * NVH) ? Ws[k * NVH + nn] : 0.f;
        }
        ((uint4*)Wp)[idx] = pack4(w);
    }
}

// 3-term bf16x2 mainloop; b-frags loaded in chunks of <=13 to bound registers
template<int KST, int KP, int NT, bool RELU>
__device__ __forceinline__ void mma_main(const float* __restrict__ Ab,
                                         const float* __restrict__ Wp,
                                         int lane, float acc[][4]) {
    const int g = lane >> 2, tg = lane & 3;
    #pragma unroll
    for (int ks = 0; ks < KST; ks++) {
        int k0 = ks * 16 + 2 * tg;
        float2 p0 = *(const float2*)(Ab + g * KP + k0);
        float2 p1 = *(const float2*)(Ab + (g + 8) * KP + k0);
        float2 p2 = *(const float2*)(Ab + g * KP + k0 + 8);
        float2 p3 = *(const float2*)(Ab + (g + 8) * KP + k0 + 8);
        unsigned ah0, ah1, ah2, ah3, al0, al1, al2, al3;
        split2<RELU>(p0, ah0, al0);
        split2<RELU>(p1, ah1, al1);
        split2<RELU>(p2, ah2, al2);
        split2<RELU>(p3, ah3, al3);
        const uint4* wrow = (const uint4*)Wp + ks * NT * 32 + lane;
        #pragma unroll
        for (int c0 = 0; c0 < NT; c0 += 13) {
            uint4 b[13];
            #pragma unroll
            for (int q = 0; q < 13; q++)
                if (c0 + q < NT) b[q] = wrow[(c0 + q) * 32];
            #pragma unroll
            for (int q = 0; q < 13; q++)
                if (c0 + q < NT) mma16b(acc[c0 + q], ah0, ah1, ah2, ah3, b[q].x, b[q].y);
            #pragma unroll
            for (int q = 0; q < 13; q++)
                if (c0 + q < NT) mma16b(acc[c0 + q], al0, al1, al2, al3, b[q].x, b[q].y);
            #pragma unroll
            for (int q = 0; q < 13; q++)
                if (c0 + q < NT) mma16b(acc[c0 + q], ah0, ah1, ah2, ah3, b[q].z, b[q].w);
        }
    }
}

// async copy of one A tile; zero-fills pad + OOB rows
template<int KIN, int KP, int ROWS, int NTHR>
__device__ __forceinline__ void prefetch_tile(const float* __restrict__ A, int M,
                                              int t, float* db, int tid) {
    constexpr int CH = KP / 4;
    const int row0 = t * ROWS;
    for (int idx = tid; idx < ROWS * CH; idx += NTHR) {
        int r = idx / CH, c = idx - r * CH;
        int grow = row0 + r;
        unsigned sa = (unsigned)__cvta_generic_to_shared(db + r * KP + c * 4);
        int nb = 0;
        const float* gs = A;
        if (grow < M) {
            int col = c * 4;
            nb = KIN - col;
            nb = nb < 0 ? 0 : (nb > 4 ? 4 : nb);
            nb *= 4;
            gs = A + (size_t)grow * KIN + (col < KIN ? col : 0);
        }
        asm volatile("cp.async.cg.shared.global [%0], [%1], 16, %2;"
                     :: "r"(sa), "l"(gs), "r"(nb));
    }
    asm volatile("cp.async.commit_group;");
}

// ---------------- standard GEMM (persistent, 128-row tiles, double-buffered) --
// EPI: 0 store+bias, 4 raw store, 6 store+bias then scatter msg=relu(h[src]+v) -> agg[dst]
// PRO: 0 none, 2 relu applied in mainloop
template<int KIN, int KST, int KP, int NT, int NV, int EPI, int PRO, bool DUALW>
__global__ void __launch_bounds__(256)
tgemm_k(const float* __restrict__ A, const float* __restrict__ W,
        const float* __restrict__ Wb, const float* __restrict__ bias,
        float* __restrict__ C, int M,
        const int* __restrict__ src, const int* __restrict__ dst,
        const float* __restrict__ hgat, float* __restrict__ agg) {
    constexpr int WFRAG = KST * NT * 128;
    constexpr int ATILE = 128 * KP;
    extern __shared__ float sm[];
    float* Wp = sm;
    float* As = sm + WFRAG;
    const int tid  = threadIdx.x;
    const int lane = tid & 31, warp = tid >> 5;
    const int g = lane >> 2, tg = lane & 3;

    if (DUALW) pack_w2<KIN, KST, NT, NV / 2, 256>(W, Wb, Wp, tid);
    else       pack_w <KIN, KST, NT, NV,     256>(W, Wp, tid);

    const int ntile = (M + 127) >> 7;
    if (blockIdx.x >= ntile) return;
    prefetch_tile<KIN, KP, 128, 256>(A, M, blockIdx.x, As, tid);
    __syncthreads();

    int buf = 0;
    for (int t = blockIdx.x; t < ntile; t += gridDim.x) {
        int tn = t + gridDim.x;
        if (tn < ntile) {
            prefetch_tile<KIN, KP, 128, 256>(A, M, tn, As + (buf ^ 1) * ATILE, tid);
            asm volatile("cp.async.wait_group 1;");
        } else {
            asm volatile("cp.async.wait_group 0;");
        }
        __syncthreads();

        const float* Ab = As + buf * ATILE + warp * 16 * KP;
        float acc[NT][4];
        #pragma unroll
        for (int nt = 0; nt < NT; nt++)
            acc[nt][0] = acc[nt][1] = acc[nt][2] = acc[nt][3] = 0.f;

        mma_main<KST, KP, NT, PRO == 2>(Ab, Wp, lane, acc);

        int rbase = t * 128 + warp * 16;
        #pragma unroll
        for (int half = 0; half < 2; half++) {
            int row = rbase + g + half * 8;
            bool rok = row < M;
            int s = 0, d = 0;
            if (EPI == 6 && rok) { s = src[row]; d = dst[row]; }
            #pragma unroll
            for (int nt = 0; nt < NT; nt++) {
                int n = nt * 8 + tg * 2;
                if (rok && n < NV) {
                    float v0 = acc[nt][half * 2 + 0];
                    float v1 = acc[nt][half * 2 + 1];
                    float2* cp = (float2*)(C + (size_t)row * NV + n);
                    if (EPI == 0) {
                        float2 bs = *(const float2*)(bias + n);
                        *cp = make_float2(v0 + bs.x, v1 + bs.y);
                    } else if (EPI == 4) {
                        *cp = make_float2(v0, v1);
                    } else if (EPI == 6) {
                        float2 bs = *(const float2*)(bias + n);
                        float2 st = make_float2(v0 + bs.x, v1 + bs.y);
                        *cp = st;
                        float2 hv = *(const float2*)(hgat + (size_t)s * Hh + n);
                        float m0 = hv.x + st.x, m1 = hv.y + st.y;
                        float* ar = agg + (size_t)d * Hh + n;
                        if (m0 > 0.f) atomicAdd(ar, m0);
                        if (m1 > 0.f) atomicAdd(ar + 1, m1);
                    }
                }
            }
        }
        buf ^= 1;
        __syncthreads();
    }
}

// ---------------- fused double GEMM -------------------------------------------
// MODE 0 (gine): t=relu(zin@W1+b1) in smem; z = t@W2+b2 -> store + BN stats
// MODE 1 (edge): t=relu(e@W1+b1+Hab[src]+Hab[dst]); e += 0.5*(t@W2+b2);
//                if SCAT: msg=relu(h[src]+e_new) atomically added to agg[dst]
template<int MODE, bool SCAT>
__global__ void __launch_bounds__(256)
dgemm_k(const float* __restrict__ A,
        const float* __restrict__ W1, const float* __restrict__ b1,
        const float* __restrict__ W2, const float* __restrict__ b2,
        float* __restrict__ C,
        const int* __restrict__ src, const int* __restrict__ dst,
        const float* __restrict__ Hab,
        const float* __restrict__ hgat, float* __restrict__ agg,
        float* __restrict__ stats, int M) {
    constexpr int KST = 7, KP = 116, NT = 13, NV = 100;
    constexpr int WFRAG = KST * NT * 128;
    extern __shared__ float sm[];
    float* Wp1 = sm;
    float* Wp2 = sm + WFRAG;
    float* As  = sm + 2 * WFRAG;
    float* Ts  = As + 128 * KP;
    __shared__ float sst[2 * Hh];
    const int tid  = threadIdx.x;
    const int lane = tid & 31, warp = tid >> 5;
    const int g = lane >> 2, tg = lane & 3;

    if (MODE == 0)
        for (int i = tid; i < 2 * Hh; i += 256) sst[i] = 0.f;
    pack_w<100, KST, NT, NV, 256>(W1, Wp1, tid);
    pack_w<100, KST, NT, NV, 256>(W2, Wp2, tid);
    // zero Ts K-pad columns once (mid-epilogue never writes them)
    for (int idx = tid; idx < 128 * (KP - 100); idx += 256) {
        int r = idx / (KP - 100), c = 100 + idx % (KP - 100);
        Ts[r * KP + c] = 0.f;
    }

    const int ntile = (M + 127) >> 7;
    if (blockIdx.x >= ntile) return;
    prefetch_tile<100, KP, 128, 256>(A, M, blockIdx.x, As, tid);
    __syncthreads();

    for (int t = blockIdx.x; t < ntile; t += gridDim.x) {
        asm volatile("cp.async.wait_group 0;");
        __syncthreads();

        const float* Ab = As + warp * 16 * KP;
        float acc[NT][4];
        #pragma unroll
        for (int nt = 0; nt < NT; nt++)
            acc[nt][0] = acc[nt][1] = acc[nt][2] = acc[nt][3] = 0.f;
        mma_main<KST, KP, NT, false>(Ab, Wp1, lane, acc);
        __syncthreads();   // all warps done reading As

        int tn = t + gridDim.x;
        if (tn < ntile) prefetch_tile<100, KP, 128, 256>(A, M, tn, As, tid);

        int rbase = t * 128 + warp * 16;
        #pragma unroll
        for (int half = 0; half < 2; half++) {
            int rl = warp * 16 + g + half * 8;
            int row = rbase + g + half * 8;
            bool rok = row < M;
            const float* ta = nullptr; const float* tb = nullptr;
            if (MODE == 1 && rok) {
                ta = Hab + (size_t)src[row] * 200;
                tb = Hab + (size_t)dst[row] * 200 + 100;
            }
            #pragma unroll
            for (int nt = 0; nt < NT; nt++) {
                int n = nt * 8 + tg * 2;
                if (n < NV) {
                    float v0 = 0.f, v1 = 0.f;
                    if (rok) {
                        float2 bs = *(const float2*)(b1 + n);
                        v0 = acc[nt][half * 2 + 0] + bs.x;
                        v1 = acc[nt][half * 2 + 1] + bs.y;
                        if (MODE == 1) {
                            float2 tav = *(const float2*)(ta + n);
                            float2 tbv = *(const float2*)(tb + n);
                            v0 += tav.x + tbv.x;
                            v1 += tav.y + tbv.y;
                        }
                        v0 = fmaxf(v0, 0.f); v1 = fmaxf(v1, 0.f);
                    }
                    *(float2*)(Ts + rl * KP + n) = make_float2(v0, v1);
                }
            }
        }
        __syncthreads();

        const float* Tab = Ts + warp * 16 * KP;
        float acc2[NT][4];
        #pragma unroll
        for (int nt = 0; nt < NT; nt++)
            acc2[nt][0] = acc2[nt][1] = acc2[nt][2] = acc2[nt][3] = 0.f;
        mma_main<KST, KP, NT, false>(Tab, Wp2, lane, acc2);

        #pragma unroll
        for (int half = 0; half < 2; half++) {
            int row = rbase + g + half * 8;
            if (row < M) {
                int s = 0, d = 0;
                if (MODE == 1 && SCAT) { s = src[row]; d = dst[row]; }
                #pragma unroll
                for (int nt = 0; nt < NT; nt++) {
                    int n = nt * 8 + tg * 2;
                    if (n < NV) {
                        float2 bs = *(const float2*)(b2 + n);
                        float v0 = acc2[nt][half * 2 + 0] + bs.x;
                        float v1 = acc2[nt][half * 2 + 1] + bs.y;
                        float2* cp = (float2*)(C + (size_t)row * NV + n);
                        if (MODE == 0) {
                            *cp = make_float2(v0, v1);
                            atomicAdd(&sst[n], v0);
                            atomicAdd(&sst[Hh + n], v0 * v0);
                            atomicAdd(&sst[n + 1], v1);
                            atomicAdd(&sst[Hh + n + 1], v1 * v1);
                        } else {
                            float2 old = *cp;   // old e: L2-hot (read this iter)
                            float2 ne = make_float2(fmaf(0.5f, v0, old.x),
                                                    fmaf(0.5f, v1, old.y));
                            *cp = ne;
                            if (SCAT) {
                                float2 hv = *(const float2*)(hgat + (size_t)s * Hh + n);
                                float m0 = hv.x + ne.x, m1 = hv.y + ne.y;
                                float* ar = agg + (size_t)d * Hh + n;
                                if (m0 > 0.f) atomicAdd(ar, m0);
                                if (m1 > 0.f) atomicAdd(ar + 1, m1);
                            }
                        }
                    }
                }
            }
        }
        __syncthreads();
    }
    if (MODE == 0) {
        for (int i = tid; i < 2 * Hh; i += 256) atomicAdd(&stats[i], sst[i]);
    }
}

// ---------------- fused o1 GEMM + final MLP -----------------------------------
// o1 = relu(e@Wc + HR[src] + HR[dst](+50) + b1)  (smem tile only)
// out = relu(o1@w2+b2) @ w3 + b3
__global__ void __launch_bounds__(256)
o1final_k(const float* __restrict__ e, const float* __restrict__ Wc,
          const float* __restrict__ b1,
          const float* __restrict__ w2, const float* __restrict__ b2,
          const float* __restrict__ w3, const float* __restrict__ b3,
          const float* __restrict__ HR,
          const int* __restrict__ src, const int* __restrict__ dst,
          float* __restrict__ out) {
    constexpr int KST = 7, KP = 116, NT = 7, NV = 50, M = Ee;
    constexpr int WFRAG = KST * NT * 128;    // 6272
    constexpr int ATILE = 128 * KP;
    extern __shared__ float sm[];
    float* Wp  = sm;
    float* As  = sm + WFRAG;
    float* o1t = As + 2 * ATILE;             // 128 * 51
    float* w2s = o1t + 128 * 51;             // 1250
    float* w3s = w2s + 1250;                 // 50
    float* b2s = w3s + 50;                   // 25
    float* b3s = b2s + 25;                   // 2
    const int tid  = threadIdx.x;
    const int lane = tid & 31, warp = tid >> 5;
    const int g = lane >> 2, tg = lane & 3;

    pack_w<100, KST, NT, NV, 256>(Wc, Wp, tid);
    for (int i = tid; i < 1250; i += 256) w2s[i] = w2[i];
    if (tid < 50) w3s[tid] = w3[tid];
    if (tid < 25) b2s[tid] = b2[tid];
    if (tid < 2)  b3s[tid] = b3[tid];

    const int ntile = (M + 127) >> 7;
    prefetch_tile<100, KP, 128, 256>(e, M, blockIdx.x, As, tid);
    __syncthreads();

    int buf = 0;
    for (int t = blockIdx.x; t < ntile; t += gridDim.x) {
        int tn = t + gridDim.x;
        if (tn < ntile) {
            prefetch_tile<100, KP, 128, 256>(e, M, tn, As + (buf ^ 1) * ATILE, tid);
            asm volatile("cp.async.wait_group 1;");
        } else {
            asm volatile("cp.async.wait_group 0;");
        }
        __syncthreads();

        const float* Ab = As + buf * ATILE + warp * 16 * KP;
        float acc[NT][4];
        #pragma unroll
        for (int nt = 0; nt < NT; nt++)
            acc[nt][0] = acc[nt][1] = acc[nt][2] = acc[nt][3] = 0.f;
        mma_main<KST, KP, NT, false>(Ab, Wp, lane, acc);

        int rbase = t * 128 + warp * 16;
        #pragma unroll
        for (int half = 0; half < 2; half++) {
            int rl = warp * 16 + g + half * 8;
            int row = rbase + g + half * 8;
            bool rok = row < M;
            const float* ta = nullptr; const float* tb = nullptr;
            if (rok) {
                ta = HR + (size_t)src[row] * 100;
                tb = HR + (size_t)dst[row] * 100 + 50;
            }
            #pragma unroll
            for (int nt = 0; nt < NT; nt++) {
                int n = nt * 8 + tg * 2;
                if (n < NV) {
                    float v0 = 0.f, v1 = 0.f;
                    if (rok) {
                        float2 bs = *(const float2*)(b1 + n);
                        float2 tav = *(const float2*)(ta + n);
                        float2 tbv = *(const float2*)(tb + n);
                        v0 = fmaxf(acc[nt][half * 2 + 0] + bs.x + tav.x + tbv.x, 0.f);
                        v1 = fmaxf(acc[nt][half * 2 + 1] + bs.y + tav.y + tbv.y, 0.f);
                    }
                    o1t[rl * 51 + n] = v0;
                    o1t[rl * 51 + n + 1] = v1;
                }
            }
        }
        __syncthreads();

        // in-smem MLP: 2 threads per row split j-space, shfl-combine
        {
            int r = tid >> 1, par = tid & 1;
            int row = t * 128 + r;
            float a[50];
            #pragma unroll
            for (int k = 0; k < 50; k++) a[k] = o1t[r * 51 + k];
            float o0 = 0.f, o1v = 0.f;
            for (int j = par; j < 25; j += 2) {
                float s = b2s[j];
                #pragma unroll
                for (int k = 0; k < 50; k++) s = fmaf(a[k], w2s[k * 25 + j], s);
                s = fmaxf(s, 0.f);
                o0  = fmaf(s, w3s[2 * j],     o0);
                o1v = fmaf(s, w3s[2 * j + 1], o1v);
            }
            o0  += __shfl_xor_sync(0xFFFFFFFFu, o0, 1);
            o1v += __shfl_xor_sync(0xFFFFFFFFu, o1v, 1);
            if (par == 0 && row < M) {
                out[(size_t)row * 2]     = o0 + b3s[0];
                out[(size_t)row * 2 + 1] = o1v + b3s[1];
            }
        }
        __syncthreads();
        buf ^= 1;
    }
}

// ---------------- launcher ---------------------------------------------------
static inline int cdiv(int a, int b) { return (a + b - 1) / b; }

template<int KIN, int KST, int KP, int NT, int NV, int EPI, int PRO, bool DUALW>
static void launch_tgemm(int M, const float* A, const float* W, const float* Wb,
                         const float* bias, float* C,
                         const int* src = nullptr, const int* dst = nullptr,
                         const float* hgat = nullptr, float* agg = nullptr) {
    int smem = (KST * NT * 128 + 2 * 128 * KP) * 4;
    cudaFuncSetAttribute(tgemm_k<KIN, KST, KP, NT, NV, EPI, PRO, DUALW>,
                         cudaFuncAttributeMaxDynamicSharedMemorySize, smem);
    int ntile = cdiv(M, 128);
    int grid = ntile < 148 ? ntile : 148;
    tgemm_k<KIN, KST, KP, NT, NV, EPI, PRO, DUALW><<<grid, 256, smem>>>(
        A, W, Wb, bias, C, M, src, dst, hgat, agg);
}

template<int MODE, bool SCAT>
static void launch_dgemm(int M, const float* A,
                         const float* W1, const float* b1,
                         const float* W2, const float* b2, float* C,
                         const int* src, const int* dst, const float* Hab,
                         const float* hgat, float* agg, float* stats) {
    int smem = (2 * 7 * 13 * 128 + 2 * 128 * 116) * 4;
    cudaFuncSetAttribute(dgemm_k<MODE, SCAT>,
                         cudaFuncAttributeMaxDynamicSharedMemorySize, smem);
    int ntile = cdiv(M, 128);
    int grid = ntile < 148 ? ntile : 148;
    dgemm_k<MODE, SCAT><<<grid, 256, smem>>>(
        A, W1, b1, W2, b2, C, src, dst, Hab, hgat, agg, stats, M);
}

extern "C" void kernel_launch(void* const* d_in, const int* in_sizes, int n_in,
                              void* d_out, int out_size) {
    const float* x        = (const float*)d_in[0];
    const float* edge_attr= (const float*)d_in[1];
    const int*   ei       = (const int*)  d_in[2];
    const float* node_w   = (const float*)d_in[3];
    const float* node_b   = (const float*)d_in[4];
    const float* edge_w   = (const float*)d_in[5];
    const float* edge_b   = (const float*)d_in[6];
    const float* gw1      = (const float*)d_in[7];
    const float* gb1      = (const float*)d_in[8];
    const float* gw2      = (const float*)d_in[9];
    const float* gb2      = (const float*)d_in[10];
    const float* bng      = (const float*)d_in[11];
    const float* bnb      = (const float*)d_in[12];
    const float* ew1      = (const float*)d_in[13];
    const float* eb1      = (const float*)d_in[14];
    const float* ew2      = (const float*)d_in[15];
    const float* eb2      = (const float*)d_in[16];
    const float* mw1      = (const float*)d_in[17];
    const float* mb1      = (const float*)d_in[18];
    const float* mw2      = (const float*)d_in[19];
    const float* mb2      = (const float*)d_in[20];
    const float* mw3      = (const float*)d_in[21];
    const float* mb3      = (const float*)d_in[22];
    float* out = (float*)d_out;

    void* p;
    cudaGetSymbolAddress(&p, g_h);    float* h    = (float*)p;
    cudaGetSymbolAddress(&p, g_e);    float* e    = (float*)p;
    cudaGetSymbolAddress(&p, g_agg);  float* agg  = (float*)p;
    cudaGetSymbolAddress(&p, g_zin);  float* zin  = (float*)p;
    cudaGetSymbolAddress(&p, g_z);    float* z    = (float*)p;
    cudaGetSymbolAddress(&p, g_Hab);  float* Hab  = (float*)p;
    cudaGetSymbolAddress(&p, g_stats);float* st   = (float*)p;

    const int* src = ei;
    const int* dst = ei + Ee;

    // init
    zero2_k<<<cdiv(Nn * Hh, 256), 256>>>(agg, st);
    // node embedding
    launch_tgemm<FIN, 4, 68, 13, 100, 0, 0, false>(Nn, x, node_w, nullptr, node_b, h);
    // edge embedding + fused layer-0 scatter (msg=relu(h[src]+e) -> agg[dst])
    launch_tgemm<EIN, 1, 20, 13, 100, 6, 0, false>(Ee, edge_attr, edge_w, nullptr,
                                                   edge_b, e, src, dst, h, agg);

    for (int l = 0; l < LL; l++) {
        // zin = h + agg; zero stats
        add_st_k<<<cdiv(Nn * Hh, 256), 256>>>(h, agg, zin, st);
        // fused GINE MLP + BN stats
        launch_dgemm<0, false>(Nn, zin,
                               gw1 + (size_t)l * 10000, gb1 + l * Hh,
                               gw2 + (size_t)l * 10000, gb2 + l * Hh,
                               z, nullptr, nullptr, nullptr, nullptr, nullptr, st);
        // h update (+ zero agg for next scatter)
        hupd_k<<<cdiv(Nn * Hh, 256), 256>>>(h, z, st, agg, bng + l * Hh, bnb + l * Hh);
        // merged Ha|Hb node-level GEMM -> Hab [Nn][200]
        launch_tgemm<100, 7, 116, 25, 200, 4, 0, true>(
            Nn, h, ew1 + (size_t)l * 30000, ew1 + (size_t)l * 30000 + 10000,
            nullptr, Hab);
        // fused edge MLP; layer 0 also scatters next layer's messages
        if (l == 0)
            launch_dgemm<1, true>(Ee, e,
                                  ew1 + (size_t)l * 30000 + 20000, eb1 + l * Hh,
                                  ew2 + (size_t)l * 10000, eb2 + l * Hh,
                                  e, src, dst, Hab, h, agg, nullptr);
        else
            launch_dgemm<1, false>(Ee, e,
                                   ew1 + (size_t)l * 30000 + 20000, eb1 + l * Hh,
                                   ew2 + (size_t)l * 10000, eb2 + l * Hh,
                                   e, src, dst, Hab, nullptr, nullptr, nullptr);
    }

    // readout: merged HRa|HRb with relu(h) folded into mainloop -> Hab [Nn][100]
    launch_tgemm<100, 7, 116, 13, 100, 4, 2, true>(
        Nn, h, mw1, mw1 + 100 * 50, nullptr, Hab);
    // fused o1 GEMM + final MLP
    {
        int smem = (7 * 7 * 128 + 2 * 128 * 116 + 128 * 51 + 1250 + 50 + 25 + 2 + 1) * 4;
        cudaFuncSetAttribute(o1final_k, cudaFuncAttributeMaxDynamicSharedMemorySize, smem);
        o1final_k<<<148, 256, smem>>>(e, mw1 + 200 * 50, mb1, mw2, mb2, mw3, mb3,
                                      Hab, src, dst, out);
    }
}

// round 15
// speedup vs baseline: 1.3901x; 1.3901x over previous
#include <cuda_runtime.h>
#include <cuda_bf16.h>
#include <math.h>

#define Nn   50000
#define Ee   500000
#define FIN  64
#define EIN  16
#define Hh   100
#define LL   2
#define BN_EPS 1e-5f

// ---------------- scratch (static device globals; no allocation) -------------
__device__ float g_h   [Nn * Hh];
__device__ float g_e   [(size_t)Ee * Hh];
__device__ float g_agg [Nn * Hh];
__device__ float g_z   [Nn * Hh];
__device__ float g_Ha  [Nn * Hh];
__device__ float g_Hb  [Nn * Hh];
__device__ float g_HR  [Nn * Hh];      // merged HRa|HRb (50+50)
__device__ float g_stats[2 * Hh];

// ---------------- small kernels ----------------------------------------------
__global__ void zero2_k(float* __restrict__ agg, float* __restrict__ st) {
    int i = blockIdx.x * blockDim.x + threadIdx.x;
    if (i < Nn * Hh) agg[i] = 0.f;
    if (i < 2 * Hh) st[i] = 0.f;
}

// msg = relu(h[src] + e) scatter-added into agg[dst]; warp per edge, float4
__global__ void __launch_bounds__(256)
scatter_k(const float* __restrict__ h, const float* __restrict__ e,
          const int* __restrict__ src, const int* __restrict__ dst,
          float* __restrict__ agg) {
    int ed = blockIdx.x * 8 + (threadIdx.x >> 5);
    int lane = threadIdx.x & 31;
    if (lane >= 25) return;
    int s = src[ed], d = dst[ed];
    float4 hv = ((const float4*)(h + (size_t)s * Hh))[lane];
    float4 ev = ((const float4*)(e + (size_t)ed * Hh))[lane];
    float* ar = agg + (size_t)d * Hh + 4 * lane;
    float m0 = hv.x + ev.x, m1 = hv.y + ev.y, m2 = hv.z + ev.z, m3 = hv.w + ev.w;
    if (m0 > 0.f) atomicAdd(ar + 0, m0);
    if (m1 > 0.f) atomicAdd(ar + 1, m1);
    if (m2 > 0.f) atomicAdd(ar + 2, m2);
    if (m3 > 0.f) atomicAdd(ar + 3, m3);
}

__global__ void bn_stats_k(const float* __restrict__ z, float* __restrict__ stats) {
    int j = threadIdx.x;
    if (j >= Hh) return;
    int r0 = blockIdx.x * 256;
    int r1 = min(r0 + 256, Nn);
    float s = 0.f, ss = 0.f;
    for (int r = r0; r < r1; r++) {
        float v = z[(size_t)r * Hh + j];
        s += v;
        ss = fmaf(v, v, ss);
    }
    atomicAdd(&stats[j], s);
    atomicAdd(&stats[Hh + j], ss);
}

__global__ void hupd_k(float* __restrict__ h, const float* __restrict__ z,
                       const float* __restrict__ stats,
                       const float* __restrict__ gamma, const float* __restrict__ beta) {
    int idx = blockIdx.x * blockDim.x + threadIdx.x;
    if (idx >= Nn * Hh) return;
    int j = idx % Hh;
    float mu  = stats[j] * (1.0f / Nn);
    float var = fmaf(-mu, mu, stats[Hh + j] * (1.0f / Nn));
    float zn  = (z[idx] - mu) * rsqrtf(var + BN_EPS) * gamma[j] + beta[j];
    h[idx] = (h[idx] + fmaxf(zn, 0.f)) * 0.5f;
}

// ---------------- bf16x2 split machinery --------------------------------------
__device__ __forceinline__ void mma16b(float* c, unsigned a0, unsigned a1,
                                       unsigned a2, unsigned a3,
                                       unsigned b0, unsigned b1) {
    asm volatile(
        "mma.sync.aligned.m16n8k16.row.col.f32.bf16.bf16.f32 "
        "{%0,%1,%2,%3}, {%4,%5,%6,%7}, {%8,%9}, {%0,%1,%2,%3};"
        : "+f"(c[0]), "+f"(c[1]), "+f"(c[2]), "+f"(c[3])
        : "r"(a0), "r"(a1), "r"(a2), "r"(a3), "r"(b0), "r"(b1));
}

template<bool RELU>
__device__ __forceinline__ void split2(float2 p, unsigned& hi, unsigned& lo) {
    if (RELU) { p.x = fmaxf(p.x, 0.f); p.y = fmaxf(p.y, 0.f); }
    unsigned bx = __float_as_uint(p.x), by = __float_as_uint(p.y);
    unsigned h;
    asm("prmt.b32 %0, %1, %2, 0x7632;" : "=r"(h) : "r"(bx), "r"(by));
    float hx = __uint_as_float(bx & 0xFFFF0000u);
    float hy = __uint_as_float(by & 0xFFFF0000u);
    float lx = p.x - hx, ly = p.y - hy;
    unsigned l;
    asm("cvt.rn.bf16x2.f32 %0, %1, %2;" : "=r"(l) : "f"(ly), "f"(lx));
    hi = h; lo = l;
}

__device__ __forceinline__ uint4 pack4(const float w[4]) {
    float lo[4];
    #pragma unroll
    for (int q = 0; q < 4; q++) {
        __nv_bfloat16 hq = __float2bfloat16(w[q]);
        lo[q] = w[q] - __bfloat162float(hq);
    }
    unsigned hb[2], lb[2];
    #pragma unroll
    for (int pi = 0; pi < 2; pi++) {
        __nv_bfloat162 hh = {__float2bfloat16(w[pi * 2]), __float2bfloat16(w[pi * 2 + 1])};
        __nv_bfloat162 ll = {__float2bfloat16(lo[pi * 2]), __float2bfloat16(lo[pi * 2 + 1])};
        hb[pi] = *(unsigned*)&hh;
        lb[pi] = *(unsigned*)&ll;
    }
    return make_uint4(hb[0], hb[1], lb[0], lb[1]);
}

template<int KIN, int KST, int NT, int NV, int NTHR>
__device__ __forceinline__ void pack_w(const float* __restrict__ W, float* Wp, int tid) {
    for (int idx = tid; idx < KST * NT * 32; idx += NTHR) {
        int ks  = idx / (NT * 32);
        int rem = idx - ks * NT * 32;
        int nt = rem >> 5, l = rem & 31;
        int tg = l & 3, g = l >> 2;
        int n = nt * 8 + g;
        int k0 = ks * 16 + 2 * tg;
        float w[4];
        #pragma unroll
        for (int q = 0; q < 4; q++) {
            int k = k0 + (q >> 1) * 8 + (q & 1);
            w[q] = (k < KIN && n < NV) ? W[k * NV + n] : 0.f;
        }
        ((uint4*)Wp)[idx] = pack4(w);
    }
}

// pack two W halves side by side (col-blocks of NVH each)
template<int KIN, int KST, int NT, int NVH, int NTHR>
__device__ __forceinline__ void pack_w2(const float* __restrict__ W1,
                                        const float* __restrict__ W2,
                                        float* Wp, int tid) {
    for (int idx = tid; idx < KST * NT * 32; idx += NTHR) {
        int ks  = idx / (NT * 32);
        int rem = idx - ks * NT * 32;
        int nt = rem >> 5, l = rem & 31;
        int tg = l & 3, g = l >> 2;
        int n = nt * 8 + g;
        int k0 = ks * 16 + 2 * tg;
        const float* Ws = (n < NVH) ? W1 : W2;
        int nn = (n < NVH) ? n : n - NVH;
        float w[4];
        #pragma unroll
        for (int q = 0; q < 4; q++) {
            int k = k0 + (q >> 1) * 8 + (q & 1);
            w[q] = (k < KIN && n < 2 * NVH) ? Ws[k * NVH + nn] : 0.f;
        }
        ((uint4*)Wp)[idx] = pack4(w);
    }
}

// 3-term bf16x2 mainloop
template<int KST, int KP, int NT, bool RELU>
__device__ __forceinline__ void mma_main(const float* __restrict__ Ab,
                                         const float* __restrict__ Wp,
                                         int lane, float acc[][4]) {
    const int g = lane >> 2, tg = lane & 3;
    #pragma unroll
    for (int ks = 0; ks < KST; ks++) {
        int k0 = ks * 16 + 2 * tg;
        float2 p0 = *(const float2*)(Ab + g * KP + k0);
        float2 p1 = *(const float2*)(Ab + (g + 8) * KP + k0);
        float2 p2 = *(const float2*)(Ab + g * KP + k0 + 8);
        float2 p3 = *(const float2*)(Ab + (g + 8) * KP + k0 + 8);
        unsigned ah0, ah1, ah2, ah3, al0, al1, al2, al3;
        split2<RELU>(p0, ah0, al0);
        split2<RELU>(p1, ah1, al1);
        split2<RELU>(p2, ah2, al2);
        split2<RELU>(p3, ah3, al3);
        const uint4* wrow = (const uint4*)Wp + ks * NT * 32 + lane;
        uint4 b[NT];
        #pragma unroll
        for (int nt = 0; nt < NT; nt++) b[nt] = wrow[nt * 32];
        #pragma unroll
        for (int nt = 0; nt < NT; nt++)
            mma16b(acc[nt], ah0, ah1, ah2, ah3, b[nt].x, b[nt].y);   // hi*hi
        #pragma unroll
        for (int nt = 0; nt < NT; nt++)
            mma16b(acc[nt], al0, al1, al2, al3, b[nt].x, b[nt].y);   // lo*hi
        #pragma unroll
        for (int nt = 0; nt < NT; nt++)
            mma16b(acc[nt], ah0, ah1, ah2, ah3, b[nt].z, b[nt].w);   // hi*lo
    }
}

// async copy of one A tile; zero-fills pad + OOB rows
template<int KIN, int KP, int ROWS, int NTHR>
__device__ __forceinline__ void prefetch_tile(const float* __restrict__ A, int M,
                                              int t, float* db, int tid) {
    constexpr int CH = KP / 4;
    const int row0 = t * ROWS;
    for (int idx = tid; idx < ROWS * CH; idx += NTHR) {
        int r = idx / CH, c = idx - r * CH;
        int grow = row0 + r;
        unsigned sa = (unsigned)__cvta_generic_to_shared(db + r * KP + c * 4);
        int nb = 0;
        const float* gs = A;
        if (grow < M) {
            int col = c * 4;
            nb = KIN - col;
            nb = nb < 0 ? 0 : (nb > 4 ? 4 : nb);
            nb *= 4;
            gs = A + (size_t)grow * KIN + (col < KIN ? col : 0);
        }
        asm volatile("cp.async.cg.shared.global [%0], [%1], 16, %2;"
                     :: "r"(sa), "l"(gs), "r"(nb));
    }
    asm volatile("cp.async.commit_group;");
}

// ---------------- standard GEMM (persistent, 128-row tiles, double-buffered) --
// EPI: 0 store+bias, 4 raw store.  PRO: 0 none, 2 relu in mainloop.
template<int KIN, int KST, int KP, int NT, int NV, int EPI, int PRO, bool DUALW>
__global__ void __launch_bounds__(256)
tgemm_k(const float* __restrict__ A, const float* __restrict__ W,
        const float* __restrict__ Wb, const float* __restrict__ bias,
        float* __restrict__ C, int M) {
    constexpr int WFRAG = KST * NT * 128;
    constexpr int ATILE = 128 * KP;
    extern __shared__ float sm[];
    float* Wp = sm;
    float* As = sm + WFRAG;
    const int tid  = threadIdx.x;
    const int lane = tid & 31, warp = tid >> 5;
    const int g = lane >> 2, tg = lane & 3;

    if (DUALW) pack_w2<KIN, KST, NT, NV / 2, 256>(W, Wb, Wp, tid);
    else       pack_w <KIN, KST, NT, NV,     256>(W, Wp, tid);

    const int ntile = (M + 127) >> 7;
    if (blockIdx.x >= ntile) return;
    prefetch_tile<KIN, KP, 128, 256>(A, M, blockIdx.x, As, tid);
    __syncthreads();

    int buf = 0;
    for (int t = blockIdx.x; t < ntile; t += gridDim.x) {
        int tn = t + gridDim.x;
        if (tn < ntile) {
            prefetch_tile<KIN, KP, 128, 256>(A, M, tn, As + (buf ^ 1) * ATILE, tid);
            asm volatile("cp.async.wait_group 1;");
        } else {
            asm volatile("cp.async.wait_group 0;");
        }
        __syncthreads();

        const float* Ab = As + buf * ATILE + warp * 16 * KP;
        float acc[NT][4];
        #pragma unroll
        for (int nt = 0; nt < NT; nt++)
            acc[nt][0] = acc[nt][1] = acc[nt][2] = acc[nt][3] = 0.f;

        mma_main<KST, KP, NT, PRO == 2>(Ab, Wp, lane, acc);

        int rbase = t * 128 + warp * 16;
        #pragma unroll
        for (int half = 0; half < 2; half++) {
            int row = rbase + g + half * 8;
            bool rok = row < M;
            #pragma unroll
            for (int nt = 0; nt < NT; nt++) {
                int n = nt * 8 + tg * 2;
                if (rok && n < NV) {
                    float v0 = acc[nt][half * 2 + 0];
                    float v1 = acc[nt][half * 2 + 1];
                    float2* cp = (float2*)(C + (size_t)row * NV + n);
                    if (EPI == 0) {
                        float2 bs = *(const float2*)(bias + n);
                        *cp = make_float2(v0 + bs.x, v1 + bs.y);
                    } else {
                        *cp = make_float2(v0, v1);
                    }
                }
            }
        }
        buf ^= 1;
        __syncthreads();
    }
}

// ---------------- fused GINE MLP (N-sized double GEMM) ------------------------
// zin = h + agg (added in smem); t = relu(zin@W1+b1) in smem; z = t@W2+b2
__global__ void __launch_bounds__(256)
gine2_k(const float* __restrict__ h, const float* __restrict__ agg,
        const float* __restrict__ W1, const float* __restrict__ b1,
        const float* __restrict__ W2, const float* __restrict__ b2,
        float* __restrict__ z, int M) {
    constexpr int KST = 7, KP = 116, NT = 13, NV = 100;
    constexpr int WFRAG = KST * NT * 128;
    extern __shared__ float sm[];
    float* Wp1 = sm;
    float* Wp2 = sm + WFRAG;
    float* As  = sm + 2 * WFRAG;
    float* Ts  = As + 128 * KP;
    const int tid  = threadIdx.x;
    const int lane = tid & 31, warp = tid >> 5;
    const int g = lane >> 2, tg = lane & 3;

    pack_w<100, KST, NT, NV, 256>(W1, Wp1, tid);
    pack_w<100, KST, NT, NV, 256>(W2, Wp2, tid);

    const int ntile = (M + 127) >> 7;
    if (blockIdx.x >= ntile) return;

    for (int t = blockIdx.x; t < ntile; t += gridDim.x) {
        prefetch_tile<100, KP, 128, 256>(h,   M, t, As, tid);
        prefetch_tile<100, KP, 128, 256>(agg, M, t, Ts, tid);
        asm volatile("cp.async.wait_group 0;");
        __syncthreads();
        // As += Ts  (zin); pad cols are 0+0
        for (int idx = tid; idx < 128 * KP / 4; idx += 256) {
            float4 a = ((const float4*)As)[idx];
            float4 b = ((const float4*)Ts)[idx];
            ((float4*)As)[idx] = make_float4(a.x + b.x, a.y + b.y, a.z + b.z, a.w + b.w);
        }
        __syncthreads();

        const float* Ab = As + warp * 16 * KP;
        float acc[NT][4];
        #pragma unroll
        for (int nt = 0; nt < NT; nt++)
            acc[nt][0] = acc[nt][1] = acc[nt][2] = acc[nt][3] = 0.f;
        mma_main<KST, KP, NT, false>(Ab, Wp1, lane, acc);

        // t = relu(acc + b1) -> Ts (own rows only; pad cols already 0, OOB rows -> 0)
        #pragma unroll
        for (int half = 0; half < 2; half++) {
            int rl = warp * 16 + g + half * 8;
            int row = t * 128 + rl;
            bool rok = row < M;
            #pragma unroll
            for (int nt = 0; nt < NT; nt++) {
                int n = nt * 8 + tg * 2;
                if (n < NV) {
                    float v0 = 0.f, v1 = 0.f;
                    if (rok) {
                        float2 bs = *(const float2*)(b1 + n);
                        v0 = fmaxf(acc[nt][half * 2 + 0] + bs.x, 0.f);
                        v1 = fmaxf(acc[nt][half * 2 + 1] + bs.y, 0.f);
                    }
                    *(float2*)(Ts + rl * KP + n) = make_float2(v0, v1);
                }
            }
        }
        // zero Ts K-pad cols (were agg staging)
        for (int idx = tid; idx < 128 * (KP - 100); idx += 256) {
            int r = idx / (KP - 100), c = 100 + idx % (KP - 100);
            Ts[r * KP + c] = 0.f;
        }
        __syncthreads();

        const float* Tab = Ts + warp * 16 * KP;
        float acc2[NT][4];
        #pragma unroll
        for (int nt = 0; nt < NT; nt++)
            acc2[nt][0] = acc2[nt][1] = acc2[nt][2] = acc2[nt][3] = 0.f;
        mma_main<KST, KP, NT, false>(Tab, Wp2, lane, acc2);

        #pragma unroll
        for (int half = 0; half < 2; half++) {
            int row = t * 128 + warp * 16 + g + half * 8;
            if (row < M) {
                #pragma unroll
                for (int nt = 0; nt < NT; nt++) {
                    int n = nt * 8 + tg * 2;
                    if (n < NV) {
                        float2 bs = *(const float2*)(b2 + n);
                        *(float2*)(z + (size_t)row * NV + n) =
                            make_float2(acc2[nt][half * 2 + 0] + bs.x,
                                        acc2[nt][half * 2 + 1] + bs.y);
                    }
                }
            }
        }
        __syncthreads();
    }
}

// ---------------- fused edge-update double GEMM (R13 + smem old-e) ------------
// t = relu(e@W1 + b1 + Ha[src] + Hb[dst]) in smem; e += 0.5*(t@W2 + b2)
// old e read back from the As smem tile (prefetch of next tile deferred to loop end).
__global__ void __launch_bounds__(256)
fgemm_k(const float* __restrict__ W1, const float* __restrict__ b1,
        const float* __restrict__ W2, const float* __restrict__ b2,
        float* __restrict__ e,
        const int* __restrict__ src, const int* __restrict__ dst,
        const float* __restrict__ Ta, const float* __restrict__ Tb) {
    constexpr int KST = 7, KP = 116, NT = 13, NV = 100, M = Ee;
    constexpr int WFRAG = KST * NT * 128;
    extern __shared__ float sm[];
    float* Wp1 = sm;
    float* Wp2 = sm + WFRAG;
    float* As  = sm + 2 * WFRAG;
    float* Ts  = As + 128 * KP;
    const int tid  = threadIdx.x;
    const int lane = tid & 31, warp = tid >> 5;
    const int g = lane >> 2, tg = lane & 3;

    pack_w<100, KST, NT, NV, 256>(W1, Wp1, tid);
    pack_w<100, KST, NT, NV, 256>(W2, Wp2, tid);
    // Ts K-pad cols: zero once (mid-epilogue never writes them)
    for (int idx = tid; idx < 128 * (KP - 100); idx += 256) {
        int r = idx / (KP - 100), c = 100 + idx % (KP - 100);
        Ts[r * KP + c] = 0.f;
    }

    const int ntile = (M + 127) >> 7;
    if (blockIdx.x >= ntile) return;
    prefetch_tile<100, KP, 128, 256>(e, M, blockIdx.x, As, tid);

    for (int t = blockIdx.x; t < ntile; t += gridDim.x) {
        asm volatile("cp.async.wait_group 0;");
        __syncthreads();

        const float* Ab = As + warp * 16 * KP;
        float acc[NT][4];
        #pragma unroll
        for (int nt = 0; nt < NT; nt++)
            acc[nt][0] = acc[nt][1] = acc[nt][2] = acc[nt][3] = 0.f;
        mma_main<KST, KP, NT, false>(Ab, Wp1, lane, acc);

        int rbase = t * 128 + warp * 16;
        // mid-epilogue: t -> Ts (own rows; OOB rows -> 0)
        #pragma unroll
        for (int half = 0; half < 2; half++) {
            int rl = warp * 16 + g + half * 8;
            int row = rbase + g + half * 8;
            bool rok = row < M;
            const float* ta = nullptr; const float* tb = nullptr;
            if (rok) {
                ta = Ta + (size_t)src[row] * NV;
                tb = Tb + (size_t)dst[row] * NV;
            }
            #pragma unroll
            for (int nt = 0; nt < NT; nt++) {
                int n = nt * 8 + tg * 2;
                if (n < NV) {
                    float v0 = 0.f, v1 = 0.f;
                    if (rok) {
                        float2 bs = *(const float2*)(b1 + n);
                        float2 tav = *(const float2*)(ta + n);
                        float2 tbv = *(const float2*)(tb + n);
                        v0 = fmaxf(acc[nt][half * 2 + 0] + bs.x + tav.x + tbv.x, 0.f);
                        v1 = fmaxf(acc[nt][half * 2 + 1] + bs.y + tav.y + tbv.y, 0.f);
                    }
                    *(float2*)(Ts + rl * KP + n) = make_float2(v0, v1);
                }
            }
        }
        __syncthreads();

        const float* Tab = Ts + warp * 16 * KP;
        float acc2[NT][4];
        #pragma unroll
        for (int nt = 0; nt < NT; nt++)
            acc2[nt][0] = acc2[nt][1] = acc2[nt][2] = acc2[nt][3] = 0.f;
        mma_main<KST, KP, NT, false>(Tab, Wp2, lane, acc2);

        // final epilogue: e[row] += 0.5*(acc2 + b2); old e from As (still intact)
        #pragma unroll
        for (int half = 0; half < 2; half++) {
            int rl = warp * 16 + g + half * 8;
            int row = rbase + g + half * 8;
            if (row < M) {
                #pragma unroll
                for (int nt = 0; nt < NT; nt++) {
                    int n = nt * 8 + tg * 2;
                    if (n < NV) {
                        float2 bs = *(const float2*)(b2 + n);
                        float2 old = *(const float2*)(As + rl * KP + n);
                        *(float2*)(e + (size_t)row * NV + n) = make_float2(
                            fmaf(0.5f, acc2[nt][half * 2 + 0] + bs.x, old.x),
                            fmaf(0.5f, acc2[nt][half * 2 + 1] + bs.y, old.y));
                    }
                }
            }
        }
        __syncthreads();   // all reads of As/Ts done before refill

        int tn = t + gridDim.x;
        if (tn < ntile) prefetch_tile<100, KP, 128, 256>(e, M, tn, As, tid);
    }
}

// ---------------- fused o1 GEMM + final MLP -----------------------------------
// o1 = relu(e@Wc + HR[src](0:50) + HR[dst](50:100) + b1) in smem;
// out = relu(o1@w2+b2) @ w3 + b3
__global__ void __launch_bounds__(256)
o1final_k(const float* __restrict__ e, const float* __restrict__ Wc,
          const float* __restrict__ b1,
          const float* __restrict__ w2, const float* __restrict__ b2,
          const float* __restrict__ w3, const float* __restrict__ b3,
          const float* __restrict__ HR,
          const int* __restrict__ src, const int* __restrict__ dst,
          float* __restrict__ out) {
    constexpr int KST = 7, KP = 116, NT = 7, NV = 50, M = Ee;
    constexpr int WFRAG = KST * NT * 128;
    constexpr int ATILE = 128 * KP;
    extern __shared__ float sm[];
    float* Wp  = sm;
    float* As  = sm + WFRAG;
    float* o1t = As + 2 * ATILE;             // 128 * 51
    float* w2s = o1t + 128 * 51;
    float* w3s = w2s + 1250;
    float* b2s = w3s + 50;
    float* b3s = b2s + 25;
    const int tid  = threadIdx.x;
    const int lane = tid & 31, warp = tid >> 5;
    const int g = lane >> 2, tg = lane & 3;

    pack_w<100, KST, NT, NV, 256>(Wc, Wp, tid);
    for (int i = tid; i < 1250; i += 256) w2s[i] = w2[i];
    if (tid < 50) w3s[tid] = w3[tid];
    if (tid < 25) b2s[tid] = b2[tid];
    if (tid < 2)  b3s[tid] = b3[tid];

    const int ntile = (M + 127) >> 7;
    prefetch_tile<100, KP, 128, 256>(e, M, blockIdx.x, As, tid);
    __syncthreads();

    int buf = 0;
    for (int t = blockIdx.x; t < ntile; t += gridDim.x) {
        int tn = t + gridDim.x;
        if (tn < ntile) {
            prefetch_tile<100, KP, 128, 256>(e, M, tn, As + (buf ^ 1) * ATILE, tid);
            asm volatile("cp.async.wait_group 1;");
        } else {
            asm volatile("cp.async.wait_group 0;");
        }
        __syncthreads();

        const float* Ab = As + buf * ATILE + warp * 16 * KP;
        float acc[NT][4];
        #pragma unroll
        for (int nt = 0; nt < NT; nt++)
            acc[nt][0] = acc[nt][1] = acc[nt][2] = acc[nt][3] = 0.f;
        mma_main<KST, KP, NT, false>(Ab, Wp, lane, acc);

        int rbase = t * 128 + warp * 16;
        #pragma unroll
        for (int half = 0; half < 2; half++) {
            int rl = warp * 16 + g + half * 8;
            int row = rbase + g + half * 8;
            bool rok = row < M;
            const float* ta = nullptr; const float* tb = nullptr;
            if (rok) {
                ta = HR + (size_t)src[row] * 100;
                tb = HR + (size_t)dst[row] * 100 + 50;
            }
            #pragma unroll
            for (int nt = 0; nt < NT; nt++) {
                int n = nt * 8 + tg * 2;
                if (n < NV) {
                    float v0 = 0.f, v1 = 0.f;
                    if (rok) {
                        float2 bs = *(const float2*)(b1 + n);
                        float2 tav = *(const float2*)(ta + n);
                        float2 tbv = *(const float2*)(tb + n);
                        v0 = fmaxf(acc[nt][half * 2 + 0] + bs.x + tav.x + tbv.x, 0.f);
                        v1 = fmaxf(acc[nt][half * 2 + 1] + bs.y + tav.y + tbv.y, 0.f);
                    }
                    o1t[rl * 51 + n] = v0;
                    o1t[rl * 51 + n + 1] = v1;
                }
            }
        }
        __syncthreads();

        // in-smem MLP: 2 threads per row, shfl-combine
        {
            int r = tid >> 1, par = tid & 1;
            int row = t * 128 + r;
            float a[50];
            #pragma unroll
            for (int k = 0; k < 50; k++) a[k] = o1t[r * 51 + k];
            float o0 = 0.f, o1v = 0.f;
            for (int j = par; j < 25; j += 2) {
                float s = b2s[j];
                #pragma unroll
                for (int k = 0; k < 50; k++) s = fmaf(a[k], w2s[k * 25 + j], s);
                s = fmaxf(s, 0.f);
                o0  = fmaf(s, w3s[2 * j],     o0);
                o1v = fmaf(s, w3s[2 * j + 1], o1v);
            }
            o0  += __shfl_xor_sync(0xFFFFFFFFu, o0, 1);
            o1v += __shfl_xor_sync(0xFFFFFFFFu, o1v, 1);
            if (par == 0 && row < M) {
                out[(size_t)row * 2]     = o0 + b3s[0];
                out[(size_t)row * 2 + 1] = o1v + b3s[1];
            }
        }
        __syncthreads();
        buf ^= 1;
    }
}

// ---------------- launcher ---------------------------------------------------
static inline int cdiv(int a, int b) { return (a + b - 1) / b; }

template<int KIN, int KST, int KP, int NT, int NV, int EPI, int PRO, bool DUALW>
static void launch_tgemm(int M, const float* A, const float* W, const float* Wb,
                         const float* bias, float* C) {
    int smem = (KST * NT * 128 + 2 * 128 * KP) * 4;
    cudaFuncSetAttribute(tgemm_k<KIN, KST, KP, NT, NV, EPI, PRO, DUALW>,
                         cudaFuncAttributeMaxDynamicSharedMemorySize, smem);
    int ntile = cdiv(M, 128);
    int grid = ntile < 148 ? ntile : 148;
    tgemm_k<KIN, KST, KP, NT, NV, EPI, PRO, DUALW><<<grid, 256, smem>>>(
        A, W, Wb, bias, C, M);
}

extern "C" void kernel_launch(void* const* d_in, const int* in_sizes, int n_in,
                              void* d_out, int out_size) {
    const float* x        = (const float*)d_in[0];
    const float* edge_attr= (const float*)d_in[1];
    const int*   ei       = (const int*)  d_in[2];
    const float* node_w   = (const float*)d_in[3];
    const float* node_b   = (const float*)d_in[4];
    const float* edge_w   = (const float*)d_in[5];
    const float* edge_b   = (const float*)d_in[6];
    const float* gw1      = (const float*)d_in[7];
    const float* gb1      = (const float*)d_in[8];
    const float* gw2      = (const float*)d_in[9];
    const float* gb2      = (const float*)d_in[10];
    const float* bng      = (const float*)d_in[11];
    const float* bnb      = (const float*)d_in[12];
    const float* ew1      = (const float*)d_in[13];
    const float* eb1      = (const float*)d_in[14];
    const float* ew2      = (const float*)d_in[15];
    const float* eb2      = (const float*)d_in[16];
    const float* mw1      = (const float*)d_in[17];
    const float* mb1      = (const float*)d_in[18];
    const float* mw2      = (const float*)d_in[19];
    const float* mb2      = (const float*)d_in[20];
    const float* mw3      = (const float*)d_in[21];
    const float* mb3      = (const float*)d_in[22];
    float* out = (float*)d_out;

    void* p;
    cudaGetSymbolAddress(&p, g_h);    float* h    = (float*)p;
    cudaGetSymbolAddress(&p, g_e);    float* e    = (float*)p;
    cudaGetSymbolAddress(&p, g_agg);  float* agg  = (float*)p;
    cudaGetSymbolAddress(&p, g_z);    float* z    = (float*)p;
    cudaGetSymbolAddress(&p, g_Ha);   float* Ha   = (float*)p;
    cudaGetSymbolAddress(&p, g_Hb);   float* Hb   = (float*)p;
    cudaGetSymbolAddress(&p, g_HR);   float* HR   = (float*)p;
    cudaGetSymbolAddress(&p, g_stats);float* st   = (float*)p;

    const int* src = ei;
    const int* dst = ei + Ee;

    int dsm = (2 * 7 * 13 * 128 + 2 * 128 * 116) * 4;   // gine2 / fgemm smem
    cudaFuncSetAttribute(gine2_k, cudaFuncAttributeMaxDynamicSharedMemorySize, dsm);
    cudaFuncSetAttribute(fgemm_k, cudaFuncAttributeMaxDynamicSharedMemorySize, dsm);

    zero2_k<<<cdiv(Nn * Hh, 256), 256>>>(agg, st);
    launch_tgemm<FIN, 4, 68, 13, 100, 0, 0, false>(Nn, x, node_w, nullptr, node_b, h);
    launch_tgemm<EIN, 1, 20, 13, 100, 0, 0, false>(Ee, edge_attr, edge_w, nullptr, edge_b, e);

    for (int l = 0; l < LL; l++) {
        if (l > 0) zero2_k<<<cdiv(Nn * Hh, 256), 256>>>(agg, st);
        scatter_k<<<Ee / 8, 256>>>(h, e, src, dst, agg);
        // fused GINE MLP (zin = h+agg in smem; t in smem; z out)
        gine2_k<<<148, 256, dsm>>>(h, agg,
                                   gw1 + (size_t)l * 10000, gb1 + l * Hh,
                                   gw2 + (size_t)l * 10000, gb2 + l * Hh, z, Nn);
        bn_stats_k<<<cdiv(Nn, 256), 128>>>(z, st);
        hupd_k<<<cdiv(Nn * Hh, 256), 256>>>(h, z, st, bng + l * Hh, bnb + l * Hh);
        // node-level halves of edge MLP
        launch_tgemm<100, 7, 116, 13, 100, 4, 0, false>(Nn, h, ew1 + (size_t)l * 30000, nullptr, nullptr, Ha);
        launch_tgemm<100, 7, 116, 13, 100, 4, 0, false>(Nn, h, ew1 + (size_t)l * 30000 + 10000, nullptr, nullptr, Hb);
        // fused edge MLP pair
        fgemm_k<<<148, 256, dsm>>>(ew1 + (size_t)l * 30000 + 20000, eb1 + l * Hh,
                                   ew2 + (size_t)l * 10000, eb2 + l * Hh,
                                   e, src, dst, Ha, Hb);
    }

    // readout: merged HRa|HRb with relu(h) folded into mainloop -> HR [Nn][100]
    launch_tgemm<100, 7, 116, 13, 100, 4, 2, true>(Nn, h, mw1, mw1 + 5000, nullptr, HR);
    // fused o1 GEMM + final MLP
    {
        int smem = (7 * 7 * 128 + 2 * 128 * 116 + 128 * 51 + 1250 + 50 + 25 + 2 + 1) * 4;
        cudaFuncSetAttribute(o1final_k, cudaFuncAttributeMaxDynamicSharedMemorySize, smem);
        o1final_k<<<148, 256, smem>>>(e, mw1 + 10000, mb1, mw2, mb2, mw3, mb3,
                                      HR, src, dst, out);
    }
}

// round 16
// speedup vs baseline: 1.3902x; 1.0001x over previous
#include <cuda_runtime.h>
#include <cuda_bf16.h>
#include <math.h>

#define Nn   50000
#define Ee   500000
#define FIN  64
#define EIN  16
#define Hh   100
#define LL   2
#define BN_EPS 1e-5f

// ---------------- scratch (static device globals; no allocation) -------------
__device__ float g_h   [Nn * Hh];
__device__ float g_e   [(size_t)Ee * Hh];
__device__ float g_agg [Nn * Hh];
__device__ float g_z   [Nn * Hh];
__device__ float g_Ha  [Nn * Hh];
__device__ float g_Hb  [Nn * Hh];
__device__ float g_HR  [Nn * Hh];      // merged HRa|HRb (50+50)
__device__ float g_stats[2 * Hh];

// ---------------- small kernels ----------------------------------------------
__global__ void zero2_k(float* __restrict__ agg, float* __restrict__ st) {
    int i = blockIdx.x * blockDim.x + threadIdx.x;
    if (i < Nn * Hh) agg[i] = 0.f;
    if (i < 2 * Hh) st[i] = 0.f;
}

__global__ void bn_stats_k(const float* __restrict__ z, float* __restrict__ stats) {
    int j = threadIdx.x;
    if (j >= Hh) return;
    int r0 = blockIdx.x * 256;
    int r1 = min(r0 + 256, Nn);
    float s = 0.f, ss = 0.f;
    for (int r = r0; r < r1; r++) {
        float v = z[(size_t)r * Hh + j];
        s += v;
        ss = fmaf(v, v, ss);
    }
    atomicAdd(&stats[j], s);
    atomicAdd(&stats[Hh + j], ss);
}

// h = (h + relu(batchnorm(z))) * 0.5 ; zero agg for next layer's fused scatter
__global__ void hupd_k(float* __restrict__ h, const float* __restrict__ z,
                       const float* __restrict__ stats, float* __restrict__ agg,
                       const float* __restrict__ gamma, const float* __restrict__ beta) {
    int idx = blockIdx.x * blockDim.x + threadIdx.x;
    if (idx >= Nn * Hh) return;
    int j = idx % Hh;
    float mu  = stats[j] * (1.0f / Nn);
    float var = fmaf(-mu, mu, stats[Hh + j] * (1.0f / Nn));
    float zn  = (z[idx] - mu) * rsqrtf(var + BN_EPS) * gamma[j] + beta[j];
    h[idx] = (h[idx] + fmaxf(zn, 0.f)) * 0.5f;
    agg[idx] = 0.f;
}

// ---------------- red.v2 helper -----------------------------------------------
__device__ __forceinline__ void red2(float* p, float m0, float m1) {
    if (m0 > 0.f || m1 > 0.f)
        asm volatile("red.global.add.v2.f32 [%0], {%1, %2};"
                     :: "l"(p), "f"(m0), "f"(m1) : "memory");
}

// ---------------- bf16x2 split machinery --------------------------------------
__device__ __forceinline__ void mma16b(float* c, unsigned a0, unsigned a1,
                                       unsigned a2, unsigned a3,
                                       unsigned b0, unsigned b1) {
    asm volatile(
        "mma.sync.aligned.m16n8k16.row.col.f32.bf16.bf16.f32 "
        "{%0,%1,%2,%3}, {%4,%5,%6,%7}, {%8,%9}, {%0,%1,%2,%3};"
        : "+f"(c[0]), "+f"(c[1]), "+f"(c[2]), "+f"(c[3])
        : "r"(a0), "r"(a1), "r"(a2), "r"(a3), "r"(b0), "r"(b1));
}

template<bool RELU>
__device__ __forceinline__ void split2(float2 p, unsigned& hi, unsigned& lo) {
    if (RELU) { p.x = fmaxf(p.x, 0.f); p.y = fmaxf(p.y, 0.f); }
    unsigned bx = __float_as_uint(p.x), by = __float_as_uint(p.y);
    unsigned h;
    asm("prmt.b32 %0, %1, %2, 0x7632;" : "=r"(h) : "r"(bx), "r"(by));
    float hx = __uint_as_float(bx & 0xFFFF0000u);
    float hy = __uint_as_float(by & 0xFFFF0000u);
    float lx = p.x - hx, ly = p.y - hy;
    unsigned l;
    asm("cvt.rn.bf16x2.f32 %0, %1, %2;" : "=r"(l) : "f"(ly), "f"(lx));
    hi = h; lo = l;
}

__device__ __forceinline__ uint4 pack4(const float w[4]) {
    float lo[4];
    #pragma unroll
    for (int q = 0; q < 4; q++) {
        __nv_bfloat16 hq = __float2bfloat16(w[q]);
        lo[q] = w[q] - __bfloat162float(hq);
    }
    unsigned hb[2], lb[2];
    #pragma unroll
    for (int pi = 0; pi < 2; pi++) {
        __nv_bfloat162 hh = {__float2bfloat16(w[pi * 2]), __float2bfloat16(w[pi * 2 + 1])};
        __nv_bfloat162 ll = {__float2bfloat16(lo[pi * 2]), __float2bfloat16(lo[pi * 2 + 1])};
        hb[pi] = *(unsigned*)&hh;
        lb[pi] = *(unsigned*)&ll;
    }
    return make_uint4(hb[0], hb[1], lb[0], lb[1]);
}

template<int KIN, int KST, int NT, int NV, int NTHR>
__device__ __forceinline__ void pack_w(const float* __restrict__ W, float* Wp, int tid) {
    for (int idx = tid; idx < KST * NT * 32; idx += NTHR) {
        int ks  = idx / (NT * 32);
        int rem = idx - ks * NT * 32;
        int nt = rem >> 5, l = rem & 31;
        int tg = l & 3, g = l >> 2;
        int n = nt * 8 + g;
        int k0 = ks * 16 + 2 * tg;
        float w[4];
        #pragma unroll
        for (int q = 0; q < 4; q++) {
            int k = k0 + (q >> 1) * 8 + (q & 1);
            w[q] = (k < KIN && n < NV) ? W[k * NV + n] : 0.f;
        }
        ((uint4*)Wp)[idx] = pack4(w);
    }
}

template<int KIN, int KST, int NT, int NVH, int NTHR>
__device__ __forceinline__ void pack_w2(const float* __restrict__ W1,
                                        const float* __restrict__ W2,
                                        float* Wp, int tid) {
    for (int idx = tid; idx < KST * NT * 32; idx += NTHR) {
        int ks  = idx / (NT * 32);
        int rem = idx - ks * NT * 32;
        int nt = rem >> 5, l = rem & 31;
        int tg = l & 3, g = l >> 2;
        int n = nt * 8 + g;
        int k0 = ks * 16 + 2 * tg;
        const float* Ws = (n < NVH) ? W1 : W2;
        int nn = (n < NVH) ? n : n - NVH;
        float w[4];
        #pragma unroll
        for (int q = 0; q < 4; q++) {
            int k = k0 + (q >> 1) * 8 + (q & 1);
            w[q] = (k < KIN && n < 2 * NVH) ? Ws[k * NVH + nn] : 0.f;
        }
        ((uint4*)Wp)[idx] = pack4(w);
    }
}

// 3-term bf16x2 mainloop
template<int KST, int KP, int NT, bool RELU>
__device__ __forceinline__ void mma_main(const float* __restrict__ Ab,
                                         const float* __restrict__ Wp,
                                         int lane, float acc[][4]) {
    const int g = lane >> 2, tg = lane & 3;
    #pragma unroll
    for (int ks = 0; ks < KST; ks++) {
        int k0 = ks * 16 + 2 * tg;
        float2 p0 = *(const float2*)(Ab + g * KP + k0);
        float2 p1 = *(const float2*)(Ab + (g + 8) * KP + k0);
        float2 p2 = *(const float2*)(Ab + g * KP + k0 + 8);
        float2 p3 = *(const float2*)(Ab + (g + 8) * KP + k0 + 8);
        unsigned ah0, ah1, ah2, ah3, al0, al1, al2, al3;
        split2<RELU>(p0, ah0, al0);
        split2<RELU>(p1, ah1, al1);
        split2<RELU>(p2, ah2, al2);
        split2<RELU>(p3, ah3, al3);
        const uint4* wrow = (const uint4*)Wp + ks * NT * 32 + lane;
        uint4 b[NT];
        #pragma unroll
        for (int nt = 0; nt < NT; nt++) b[nt] = wrow[nt * 32];
        #pragma unroll
        for (int nt = 0; nt < NT; nt++)
            mma16b(acc[nt], ah0, ah1, ah2, ah3, b[nt].x, b[nt].y);   // hi*hi
        #pragma unroll
        for (int nt = 0; nt < NT; nt++)
            mma16b(acc[nt], al0, al1, al2, al3, b[nt].x, b[nt].y);   // lo*hi
        #pragma unroll
        for (int nt = 0; nt < NT; nt++)
            mma16b(acc[nt], ah0, ah1, ah2, ah3, b[nt].z, b[nt].w);   // hi*lo
    }
}

// async copy of one A tile; zero-fills pad + OOB rows
template<int KIN, int KP, int ROWS, int NTHR>
__device__ __forceinline__ void prefetch_tile(const float* __restrict__ A, int M,
                                              int t, float* db, int tid) {
    constexpr int CH = KP / 4;
    const int row0 = t * ROWS;
    for (int idx = tid; idx < ROWS * CH; idx += NTHR) {
        int r = idx / CH, c = idx - r * CH;
        int grow = row0 + r;
        unsigned sa = (unsigned)__cvta_generic_to_shared(db + r * KP + c * 4);
        int nb = 0;
        const float* gs = A;
        if (grow < M) {
            int col = c * 4;
            nb = KIN - col;
            nb = nb < 0 ? 0 : (nb > 4 ? 4 : nb);
            nb *= 4;
            gs = A + (size_t)grow * KIN + (col < KIN ? col : 0);
        }
        asm volatile("cp.async.cg.shared.global [%0], [%1], 16, %2;"
                     :: "r"(sa), "l"(gs), "r"(nb));
    }
    asm volatile("cp.async.commit_group;");
}

// ---------------- standard GEMM (persistent, 128-row tiles, double-buffered) --
// EPI: 0 store+bias, 4 raw store,
//      6 store+bias THEN scatter msg=relu(hgat[src]+v) -> red.v2 agg[dst]
// PRO: 0 none, 2 relu in mainloop.
template<int KIN, int KST, int KP, int NT, int NV, int EPI, int PRO, bool DUALW>
__global__ void __launch_bounds__(256)
tgemm_k(const float* __restrict__ A, const float* __restrict__ W,
        const float* __restrict__ Wb, const float* __restrict__ bias,
        float* __restrict__ C, int M,
        const int* __restrict__ src, const int* __restrict__ dst,
        const float* __restrict__ hgat, float* __restrict__ agg) {
    constexpr int WFRAG = KST * NT * 128;
    constexpr int ATILE = 128 * KP;
    extern __shared__ float sm[];
    float* Wp = sm;
    float* As = sm + WFRAG;
    const int tid  = threadIdx.x;
    const int lane = tid & 31, warp = tid >> 5;
    const int g = lane >> 2, tg = lane & 3;

    if (DUALW) pack_w2<KIN, KST, NT, NV / 2, 256>(W, Wb, Wp, tid);
    else       pack_w <KIN, KST, NT, NV,     256>(W, Wp, tid);

    const int ntile = (M + 127) >> 7;
    if (blockIdx.x >= ntile) return;
    prefetch_tile<KIN, KP, 128, 256>(A, M, blockIdx.x, As, tid);
    __syncthreads();

    int buf = 0;
    for (int t = blockIdx.x; t < ntile; t += gridDim.x) {
        int tn = t + gridDim.x;
        if (tn < ntile) {
            prefetch_tile<KIN, KP, 128, 256>(A, M, tn, As + (buf ^ 1) * ATILE, tid);
            asm volatile("cp.async.wait_group 1;");
        } else {
            asm volatile("cp.async.wait_group 0;");
        }
        __syncthreads();

        const float* Ab = As + buf * ATILE + warp * 16 * KP;
        float acc[NT][4];
        #pragma unroll
        for (int nt = 0; nt < NT; nt++)
            acc[nt][0] = acc[nt][1] = acc[nt][2] = acc[nt][3] = 0.f;

        mma_main<KST, KP, NT, PRO == 2>(Ab, Wp, lane, acc);

        int rbase = t * 128 + warp * 16;
        #pragma unroll
        for (int half = 0; half < 2; half++) {
            int row = rbase + g + half * 8;
            bool rok = row < M;
            int s = 0, d = 0;
            if (EPI == 6 && rok) { s = src[row]; d = dst[row]; }
            #pragma unroll
            for (int nt = 0; nt < NT; nt++) {
                int n = nt * 8 + tg * 2;
                if (rok && n < NV) {
                    float v0 = acc[nt][half * 2 + 0];
                    float v1 = acc[nt][half * 2 + 1];
                    float2* cp = (float2*)(C + (size_t)row * NV + n);
                    if (EPI == 0) {
                        float2 bs = *(const float2*)(bias + n);
                        *cp = make_float2(v0 + bs.x, v1 + bs.y);
                    } else if (EPI == 4) {
                        *cp = make_float2(v0, v1);
                    } else if (EPI == 6) {
                        float2 bs = *(const float2*)(bias + n);
                        float2 ev = make_float2(v0 + bs.x, v1 + bs.y);
                        *cp = ev;
                        float2 hv = *(const float2*)(hgat + (size_t)s * Hh + n);
                        red2(agg + (size_t)d * Hh + n,
                             fmaxf(hv.x + ev.x, 0.f), fmaxf(hv.y + ev.y, 0.f));
                    }
                }
            }
        }
        buf ^= 1;
        __syncthreads();
    }
}

// ---------------- merged Ha/Hb node GEMM (one A pass, two W passes) -----------
__global__ void __launch_bounds__(256)
hab2_k(const float* __restrict__ h,
       const float* __restrict__ W1, const float* __restrict__ W2,
       float* __restrict__ Ha, float* __restrict__ Hb, int M) {
    constexpr int KST = 7, KP = 116, NT = 13, NV = 100;
    constexpr int WFRAG = KST * NT * 128;
    extern __shared__ float sm[];
    float* Wp1 = sm;
    float* Wp2 = sm + WFRAG;
    float* As  = sm + 2 * WFRAG;
    const int tid  = threadIdx.x;
    const int lane = tid & 31, warp = tid >> 5;
    const int g = lane >> 2, tg = lane & 3;

    pack_w<100, KST, NT, NV, 256>(W1, Wp1, tid);
    pack_w<100, KST, NT, NV, 256>(W2, Wp2, tid);

    const int ntile = (M + 127) >> 7;
    if (blockIdx.x >= ntile) return;
    prefetch_tile<100, KP, 128, 256>(h, M, blockIdx.x, As, tid);

    for (int t = blockIdx.x; t < ntile; t += gridDim.x) {
        asm volatile("cp.async.wait_group 0;");
        __syncthreads();

        const float* Ab = As + warp * 16 * KP;
        int rbase = t * 128 + warp * 16;

        #pragma unroll
        for (int pass = 0; pass < 2; pass++) {
            float acc[NT][4];
            #pragma unroll
            for (int nt = 0; nt < NT; nt++)
                acc[nt][0] = acc[nt][1] = acc[nt][2] = acc[nt][3] = 0.f;
            mma_main<KST, KP, NT, false>(Ab, pass ? Wp2 : Wp1, lane, acc);
            float* Cout = pass ? Hb : Ha;
            #pragma unroll
            for (int half = 0; half < 2; half++) {
                int row = rbase + g + half * 8;
                if (row < M) {
                    #pragma unroll
                    for (int nt = 0; nt < NT; nt++) {
                        int n = nt * 8 + tg * 2;
                        if (n < NV)
                            *(float2*)(Cout + (size_t)row * NV + n) =
                                make_float2(acc[nt][half * 2 + 0], acc[nt][half * 2 + 1]);
                    }
                }
            }
        }
        __syncthreads();
        int tn = t + gridDim.x;
        if (tn < ntile) prefetch_tile<100, KP, 128, 256>(h, M, tn, As, tid);
    }
}

// ---------------- fused GINE MLP (N-sized double GEMM) ------------------------
// block 0 zeroes stats first (safe: prior reader hupd already ran).
__global__ void __launch_bounds__(256)
gine2_k(const float* __restrict__ h, const float* __restrict__ agg,
        const float* __restrict__ W1, const float* __restrict__ b1,
        const float* __restrict__ W2, const float* __restrict__ b2,
        float* __restrict__ z, float* __restrict__ st, int M) {
    constexpr int KST = 7, KP = 116, NT = 13, NV = 100;
    constexpr int WFRAG = KST * NT * 128;
    extern __shared__ float sm[];
    float* Wp1 = sm;
    float* Wp2 = sm + WFRAG;
    float* As  = sm + 2 * WFRAG;
    float* Ts  = As + 128 * KP;
    const int tid  = threadIdx.x;
    const int lane = tid & 31, warp = tid >> 5;
    const int g = lane >> 2, tg = lane & 3;

    if (blockIdx.x == 0 && tid < 2 * Hh) st[tid] = 0.f;

    pack_w<100, KST, NT, NV, 256>(W1, Wp1, tid);
    pack_w<100, KST, NT, NV, 256>(W2, Wp2, tid);

    const int ntile = (M + 127) >> 7;
    if (blockIdx.x >= ntile) return;

    for (int t = blockIdx.x; t < ntile; t += gridDim.x) {
        prefetch_tile<100, KP, 128, 256>(h,   M, t, As, tid);
        prefetch_tile<100, KP, 128, 256>(agg, M, t, Ts, tid);
        asm volatile("cp.async.wait_group 0;");
        __syncthreads();
        for (int idx = tid; idx < 128 * KP / 4; idx += 256) {
            float4 a = ((const float4*)As)[idx];
            float4 b = ((const float4*)Ts)[idx];
            ((float4*)As)[idx] = make_float4(a.x + b.x, a.y + b.y, a.z + b.z, a.w + b.w);
        }
        __syncthreads();

        const float* Ab = As + warp * 16 * KP;
        float acc[NT][4];
        #pragma unroll
        for (int nt = 0; nt < NT; nt++)
            acc[nt][0] = acc[nt][1] = acc[nt][2] = acc[nt][3] = 0.f;
        mma_main<KST, KP, NT, false>(Ab, Wp1, lane, acc);

        #pragma unroll
        for (int half = 0; half < 2; half++) {
            int rl = warp * 16 + g + half * 8;
            int row = t * 128 + rl;
            bool rok = row < M;
            #pragma unroll
            for (int nt = 0; nt < NT; nt++) {
                int n = nt * 8 + tg * 2;
                if (n < NV) {
                    float v0 = 0.f, v1 = 0.f;
                    if (rok) {
                        float2 bs = *(const float2*)(b1 + n);
                        v0 = fmaxf(acc[nt][half * 2 + 0] + bs.x, 0.f);
                        v1 = fmaxf(acc[nt][half * 2 + 1] + bs.y, 0.f);
                    }
                    *(float2*)(Ts + rl * KP + n) = make_float2(v0, v1);
                }
            }
        }
        for (int idx = tid; idx < 128 * (KP - 100); idx += 256) {
            int r = idx / (KP - 100), c = 100 + idx % (KP - 100);
            Ts[r * KP + c] = 0.f;
        }
        __syncthreads();

        const float* Tab = Ts + warp * 16 * KP;
        float acc2[NT][4];
        #pragma unroll
        for (int nt = 0; nt < NT; nt++)
            acc2[nt][0] = acc2[nt][1] = acc2[nt][2] = acc2[nt][3] = 0.f;
        mma_main<KST, KP, NT, false>(Tab, Wp2, lane, acc2);

        #pragma unroll
        for (int half = 0; half < 2; half++) {
            int row = t * 128 + warp * 16 + g + half * 8;
            if (row < M) {
                #pragma unroll
                for (int nt = 0; nt < NT; nt++) {
                    int n = nt * 8 + tg * 2;
                    if (n < NV) {
                        float2 bs = *(const float2*)(b2 + n);
                        *(float2*)(z + (size_t)row * NV + n) =
                            make_float2(acc2[nt][half * 2 + 0] + bs.x,
                                        acc2[nt][half * 2 + 1] + bs.y);
                    }
                }
            }
        }
        __syncthreads();
    }
}

// ---------------- fused edge-update double GEMM -------------------------------
// t = relu(e@W1 + b1 + Ha[src] + Hb[dst]); e += 0.5*(t@W2 + b2)
// SCAT: also scatter msg=relu(hgat[src]+e_new) via red.v2 into agg[dst]
template<bool SCAT>
__global__ void __launch_bounds__(256)
fgemm_k(const float* __restrict__ W1, const float* __restrict__ b1,
        const float* __restrict__ W2, const float* __restrict__ b2,
        float* __restrict__ e,
        const int* __restrict__ src, const int* __restrict__ dst,
        const float* __restrict__ Ta, const float* __restrict__ Tb,
        const float* __restrict__ hgat, float* __restrict__ agg) {
    constexpr int KST = 7, KP = 116, NT = 13, NV = 100, M = Ee;
    constexpr int WFRAG = KST * NT * 128;
    extern __shared__ float sm[];
    float* Wp1 = sm;
    float* Wp2 = sm + WFRAG;
    float* As  = sm + 2 * WFRAG;
    float* Ts  = As + 128 * KP;
    const int tid  = threadIdx.x;
    const int lane = tid & 31, warp = tid >> 5;
    const int g = lane >> 2, tg = lane & 3;

    pack_w<100, KST, NT, NV, 256>(W1, Wp1, tid);
    pack_w<100, KST, NT, NV, 256>(W2, Wp2, tid);
    for (int idx = tid; idx < 128 * (KP - 100); idx += 256) {
        int r = idx / (KP - 100), c = 100 + idx % (KP - 100);
        Ts[r * KP + c] = 0.f;
    }

    const int ntile = (M + 127) >> 7;
    if (blockIdx.x >= ntile) return;
    prefetch_tile<100, KP, 128, 256>(e, M, blockIdx.x, As, tid);

    for (int t = blockIdx.x; t < ntile; t += gridDim.x) {
        asm volatile("cp.async.wait_group 0;");
        __syncthreads();

        const float* Ab = As + warp * 16 * KP;
        float acc[NT][4];
        #pragma unroll
        for (int nt = 0; nt < NT; nt++)
            acc[nt][0] = acc[nt][1] = acc[nt][2] = acc[nt][3] = 0.f;
        mma_main<KST, KP, NT, false>(Ab, Wp1, lane, acc);

        int rbase = t * 128 + warp * 16;
        #pragma unroll
        for (int half = 0; half < 2; half++) {
            int rl = warp * 16 + g + half * 8;
            int row = rbase + g + half * 8;
            bool rok = row < M;
            const float* ta = nullptr; const float* tb = nullptr;
            if (rok) {
                ta = Ta + (size_t)src[row] * NV;
                tb = Tb + (size_t)dst[row] * NV;
            }
            #pragma unroll
            for (int nt = 0; nt < NT; nt++) {
                int n = nt * 8 + tg * 2;
                if (n < NV) {
                    float v0 = 0.f, v1 = 0.f;
                    if (rok) {
                        float2 bs = *(const float2*)(b1 + n);
                        float2 tav = *(const float2*)(ta + n);
                        float2 tbv = *(const float2*)(tb + n);
                        v0 = fmaxf(acc[nt][half * 2 + 0] + bs.x + tav.x + tbv.x, 0.f);
                        v1 = fmaxf(acc[nt][half * 2 + 1] + bs.y + tav.y + tbv.y, 0.f);
                    }
                    *(float2*)(Ts + rl * KP + n) = make_float2(v0, v1);
                }
            }
        }
        __syncthreads();

        const float* Tab = Ts + warp * 16 * KP;
        float acc2[NT][4];
        #pragma unroll
        for (int nt = 0; nt < NT; nt++)
            acc2[nt][0] = acc2[nt][1] = acc2[nt][2] = acc2[nt][3] = 0.f;
        mma_main<KST, KP, NT, false>(Tab, Wp2, lane, acc2);

        #pragma unroll
        for (int half = 0; half < 2; half++) {
            int rl = warp * 16 + g + half * 8;
            int row = rbase + g + half * 8;
            if (row < M) {
                int s = 0, d = 0;
                if (SCAT) { s = src[row]; d = dst[row]; }
                #pragma unroll
                for (int nt = 0; nt < NT; nt++) {
                    int n = nt * 8 + tg * 2;
                    if (n < NV) {
                        float2 bs = *(const float2*)(b2 + n);
                        float2 old = *(const float2*)(As + rl * KP + n);
                        float2 ne = make_float2(
                            fmaf(0.5f, acc2[nt][half * 2 + 0] + bs.x, old.x),
                            fmaf(0.5f, acc2[nt][half * 2 + 1] + bs.y, old.y));
                        *(float2*)(e + (size_t)row * NV + n) = ne;
                        if (SCAT) {
                            float2 hv = *(const float2*)(hgat + (size_t)s * Hh + n);
                            red2(agg + (size_t)d * Hh + n,
                                 fmaxf(hv.x + ne.x, 0.f), fmaxf(hv.y + ne.y, 0.f));
                        }
                    }
                }
            }
        }
        __syncthreads();

        int tn = t + gridDim.x;
        if (tn < ntile) prefetch_tile<100, KP, 128, 256>(e, M, tn, As, tid);
    }
}

// ---------------- fused o1 GEMM + final MLP -----------------------------------
__global__ void __launch_bounds__(256)
o1final_k(const float* __restrict__ e, const float* __restrict__ Wc,
          const float* __restrict__ b1,
          const float* __restrict__ w2, const float* __restrict__ b2,
          const float* __restrict__ w3, const float* __restrict__ b3,
          const float* __restrict__ HR,
          const int* __restrict__ src, const int* __restrict__ dst,
          float* __restrict__ out) {
    constexpr int KST = 7, KP = 116, NT = 7, NV = 50, M = Ee;
    constexpr int WFRAG = KST * NT * 128;
    constexpr int ATILE = 128 * KP;
    extern __shared__ float sm[];
    float* Wp  = sm;
    float* As  = sm + WFRAG;
    float* o1t = As + 2 * ATILE;             // 128 * 51
    float* w2s = o1t + 128 * 51;
    float* w3s = w2s + 1250;
    float* b2s = w3s + 50;
    float* b3s = b2s + 25;
    const int tid  = threadIdx.x;
    const int lane = tid & 31, warp = tid >> 5;
    const int g = lane >> 2, tg = lane & 3;

    pack_w<100, KST, NT, NV, 256>(Wc, Wp, tid);
    for (int i = tid; i < 1250; i += 256) w2s[i] = w2[i];
    if (tid < 50) w3s[tid] = w3[tid];
    if (tid < 25) b2s[tid] = b2[tid];
    if (tid < 2)  b3s[tid] = b3[tid];

    const int ntile = (M + 127) >> 7;
    prefetch_tile<100, KP, 128, 256>(e, M, blockIdx.x, As, tid);
    __syncthreads();

    int buf = 0;
    for (int t = blockIdx.x; t < ntile; t += gridDim.x) {
        int tn = t + gridDim.x;
        if (tn < ntile) {
            prefetch_tile<100, KP, 128, 256>(e, M, tn, As + (buf ^ 1) * ATILE, tid);
            asm volatile("cp.async.wait_group 1;");
        } else {
            asm volatile("cp.async.wait_group 0;");
        }
        __syncthreads();

        const float* Ab = As + buf * ATILE + warp * 16 * KP;
        float acc[NT][4];
        #pragma unroll
        for (int nt = 0; nt < NT; nt++)
            acc[nt][0] = acc[nt][1] = acc[nt][2] = acc[nt][3] = 0.f;
        mma_main<KST, KP, NT, false>(Ab, Wp, lane, acc);

        int rbase = t * 128 + warp * 16;
        #pragma unroll
        for (int half = 0; half < 2; half++) {
            int rl = warp * 16 + g + half * 8;
            int row = rbase + g + half * 8;
            bool rok = row < M;
            const float* ta = nullptr; const float* tb = nullptr;
            if (rok) {
                ta = HR + (size_t)src[row] * 100;
                tb = HR + (size_t)dst[row] * 100 + 50;
            }
            #pragma unroll
            for (int nt = 0; nt < NT; nt++) {
                int n = nt * 8 + tg * 2;
                if (n < NV) {
                    float v0 = 0.f, v1 = 0.f;
                    if (rok) {
                        float2 bs = *(const float2*)(b1 + n);
                        float2 tav = *(const float2*)(ta + n);
                        float2 tbv = *(const float2*)(tb + n);
                        v0 = fmaxf(acc[nt][half * 2 + 0] + bs.x + tav.x + tbv.x, 0.f);
                        v1 = fmaxf(acc[nt][half * 2 + 1] + bs.y + tav.y + tbv.y, 0.f);
                    }
                    o1t[rl * 51 + n] = v0;
                    o1t[rl * 51 + n + 1] = v1;
                }
            }
        }
        __syncthreads();

        {
            int r = tid >> 1, par = tid & 1;
            int row = t * 128 + r;
            float a[50];
            #pragma unroll
            for (int k = 0; k < 50; k++) a[k] = o1t[r * 51 + k];
            float o0 = 0.f, o1v = 0.f;
            for (int j = par; j < 25; j += 2) {
                float s = b2s[j];
                #pragma unroll
                for (int k = 0; k < 50; k++) s = fmaf(a[k], w2s[k * 25 + j], s);
                s = fmaxf(s, 0.f);
                o0  = fmaf(s, w3s[2 * j],     o0);
                o1v = fmaf(s, w3s[2 * j + 1], o1v);
            }
            o0  += __shfl_xor_sync(0xFFFFFFFFu, o0, 1);
            o1v += __shfl_xor_sync(0xFFFFFFFFu, o1v, 1);
            if (par == 0 && row < M) {
                out[(size_t)row * 2]     = o0 + b3s[0];
                out[(size_t)row * 2 + 1] = o1v + b3s[1];
            }
        }
        __syncthreads();
        buf ^= 1;
    }
}

// ---------------- launcher ---------------------------------------------------
static inline int cdiv(int a, int b) { return (a + b - 1) / b; }

template<int KIN, int KST, int KP, int NT, int NV, int EPI, int PRO, bool DUALW>
static void launch_tgemm(int M, const float* A, const float* W, const float* Wb,
                         const float* bias, float* C,
                         const int* src = nullptr, const int* dst = nullptr,
                         const float* hgat = nullptr, float* agg = nullptr) {
    int smem = (KST * NT * 128 + 2 * 128 * KP) * 4;
    cudaFuncSetAttribute(tgemm_k<KIN, KST, KP, NT, NV, EPI, PRO, DUALW>,
                         cudaFuncAttributeMaxDynamicSharedMemorySize, smem);
    int ntile = cdiv(M, 128);
    int grid = ntile < 148 ? ntile : 148;
    tgemm_k<KIN, KST, KP, NT, NV, EPI, PRO, DUALW><<<grid, 256, smem>>>(
        A, W, Wb, bias, C, M, src, dst, hgat, agg);
}

extern "C" void kernel_launch(void* const* d_in, const int* in_sizes, int n_in,
                              void* d_out, int out_size) {
    const float* x        = (const float*)d_in[0];
    const float* edge_attr= (const float*)d_in[1];
    const int*   ei       = (const int*)  d_in[2];
    const float* node_w   = (const float*)d_in[3];
    const float* node_b   = (const float*)d_in[4];
    const float* edge_w   = (const float*)d_in[5];
    const float* edge_b   = (const float*)d_in[6];
    const float* gw1      = (const float*)d_in[7];
    const float* gb1      = (const float*)d_in[8];
    const float* gw2      = (const float*)d_in[9];
    const float* gb2      = (const float*)d_in[10];
    const float* bng      = (const float*)d_in[11];
    const float* bnb      = (const float*)d_in[12];
    const float* ew1      = (const float*)d_in[13];
    const float* eb1      = (const float*)d_in[14];
    const float* ew2      = (const float*)d_in[15];
    const float* eb2      = (const float*)d_in[16];
    const float* mw1      = (const float*)d_in[17];
    const float* mb1      = (const float*)d_in[18];
    const float* mw2      = (const float*)d_in[19];
    const float* mb2      = (const float*)d_in[20];
    const float* mw3      = (const float*)d_in[21];
    const float* mb3      = (const float*)d_in[22];
    float* out = (float*)d_out;

    void* p;
    cudaGetSymbolAddress(&p, g_h);    float* h    = (float*)p;
    cudaGetSymbolAddress(&p, g_e);    float* e    = (float*)p;
    cudaGetSymbolAddress(&p, g_agg);  float* agg  = (float*)p;
    cudaGetSymbolAddress(&p, g_z);    float* z    = (float*)p;
    cudaGetSymbolAddress(&p, g_Ha);   float* Ha   = (float*)p;
    cudaGetSymbolAddress(&p, g_Hb);   float* Hb   = (float*)p;
    cudaGetSymbolAddress(&p, g_HR);   float* HR   = (float*)p;
    cudaGetSymbolAddress(&p, g_stats);float* st   = (float*)p;

    const int* src = ei;
    const int* dst = ei + Ee;

    int dsm = (2 * 7 * 13 * 128 + 2 * 128 * 116) * 4;   // 212 KB
    cudaFuncSetAttribute(gine2_k, cudaFuncAttributeMaxDynamicSharedMemorySize, dsm);
    cudaFuncSetAttribute(fgemm_k<true>,  cudaFuncAttributeMaxDynamicSharedMemorySize, dsm);
    cudaFuncSetAttribute(fgemm_k<false>, cudaFuncAttributeMaxDynamicSharedMemorySize, dsm);
    int hsm = (2 * 7 * 13 * 128 + 128 * 116) * 4;
    cudaFuncSetAttribute(hab2_k, cudaFuncAttributeMaxDynamicSharedMemorySize, hsm);

    // init: agg=0, st=0
    zero2_k<<<cdiv(Nn * Hh, 256), 256>>>(agg, st);
    // node embedding
    launch_tgemm<FIN, 4, 68, 13, 100, 0, 0, false>(Nn, x, node_w, nullptr, node_b, h);
    // edge embedding + fused layer-0 scatter (red.v2 into agg)
    launch_tgemm<EIN, 1, 20, 13, 100, 6, 0, false>(Ee, edge_attr, edge_w, nullptr,
                                                   edge_b, e, src, dst, h, agg);

    for (int l = 0; l < LL; l++) {
        // fused GINE MLP (block0 zeroes st first; prior reader hupd done)
        gine2_k<<<148, 256, dsm>>>(h, agg,
                                   gw1 + (size_t)l * 10000, gb1 + l * Hh,
                                   gw2 + (size_t)l * 10000, gb2 + l * Hh, z, st, Nn);
        bn_stats_k<<<cdiv(Nn, 256), 128>>>(z, st);
        hupd_k<<<cdiv(Nn * Hh, 256), 256>>>(h, z, st, agg, bng + l * Hh, bnb + l * Hh);
        // merged node-level halves of edge MLP
        hab2_k<<<148, 256, hsm>>>(h, ew1 + (size_t)l * 30000,
                                  ew1 + (size_t)l * 30000 + 10000, Ha, Hb, Nn);
        // fused edge MLP; layer 0 also scatters next layer's messages
        if (l == 0)
            fgemm_k<true><<<148, 256, dsm>>>(
                ew1 + (size_t)l * 30000 + 20000, eb1 + l * Hh,
                ew2 + (size_t)l * 10000, eb2 + l * Hh,
                e, src, dst, Ha, Hb, h, agg);
        else
            fgemm_k<false><<<148, 256, dsm>>>(
                ew1 + (size_t)l * 30000 + 20000, eb1 + l * Hh,
                ew2 + (size_t)l * 10000, eb2 + l * Hh,
                e, src, dst, Ha, Hb, nullptr, nullptr);
    }

    // readout: merged HRa|HRb with relu(h) in mainloop -> HR [Nn][100]
    launch_tgemm<100, 7, 116, 13, 100, 4, 2, true>(Nn, h, mw1, mw1 + 5000, nullptr, HR);
    // fused o1 GEMM + final MLP
    {
        int smem = (7 * 7 * 128 + 2 * 128 * 116 + 128 * 51 + 1250 + 50 + 25 + 2 + 1) * 4;
        cudaFuncSetAttribute(o1final_k, cudaFuncAttributeMaxDynamicSharedMemorySize, smem);
        o1final_k<<<148, 256, smem>>>(e, mw1 + 10000, mb1, mw2, mb2, mw3, mb3,
                                      HR, src, dst, out);
    }
}